// round 1
// baseline (speedup 1.0000x reference)
#include <cuda_runtime.h>
#include <cuda_bf16.h>

// values[m] = sum_n exp(-0.5 * sum_d (p[m,d]-pos[n,d])^2 * inv_var[n,d]) * I[n]
//
// Expanded form per gaussian n (fold -0.5 and log2(e) into coefficients):
//   civ_d = -0.5 * log2(e) / (exp(ls_d)^2 + eps)
//   arg   = sum_d civ_d*(p_d - s_d)^2          (in log2 domain)
//         = sum_d [ civ_d*p_d^2 + (-2 civ_d s_d)*p_d ] + sum_d civ_d*s_d^2
//   gauss = exp2(arg)   -> single ex2.approx.f32
//
// Per-gaussian packed params: q0 = (ax, ay, az, bx), q1 = (by, bz, c, intensity)

#define MAX_N 4096  // params buffer capacity (N=1024 in this problem)

__device__ float4 g_params[2 * MAX_N];

__global__ void prep_kernel(const float* __restrict__ positions,
                            const float* __restrict__ log_scales,
                            const float* __restrict__ intensities,
                            int N) {
    int n = blockIdx.x * blockDim.x + threadIdx.x;
    if (n >= N) return;
    const float LOG2E = 1.4426950408889634f;
    float a[3], b[3];
    float c = 0.0f;
#pragma unroll
    for (int d = 0; d < 3; d++) {
        float ls = log_scales[3 * n + d];
        float s  = __expf(ls);
        float iv = 1.0f / (s * s + 1e-6f);
        float civ = -0.5f * LOG2E * iv;
        float p = positions[3 * n + d];
        a[d] = civ;
        b[d] = -2.0f * civ * p;
        c = fmaf(civ, p * p, c);
    }
    g_params[2 * n]     = make_float4(a[0], a[1], a[2], b[0]);
    g_params[2 * n + 1] = make_float4(b[1], b[2], c, intensities[n]);
}

__global__ void eval_kernel(const float* __restrict__ points,
                            float* __restrict__ out,
                            int M, int N) {
    extern __shared__ float4 sp[];  // 2*N float4s
    for (int i = threadIdx.x; i < 2 * N; i += blockDim.x) {
        sp[i] = g_params[i];
    }
    __syncthreads();

    int m = blockIdx.x * blockDim.x + threadIdx.x;
    float px = 0.f, py = 0.f, pz = 0.f;
    if (m < M) {
        px = points[3 * m + 0];
        py = points[3 * m + 1];
        pz = points[3 * m + 2];
    }
    float px2 = px * px;
    float py2 = py * py;
    float pz2 = pz * pz;

    float acc = 0.0f;
#pragma unroll 8
    for (int n = 0; n < N; n++) {
        float4 q0 = sp[2 * n];
        float4 q1 = sp[2 * n + 1];
        float arg = fmaf(q0.x, px2,
                    fmaf(q0.y, py2,
                    fmaf(q0.z, pz2,
                    fmaf(q0.w, px,
                    fmaf(q1.x, py,
                    fmaf(q1.y, pz, q1.z))))));
        float g;
        asm("ex2.approx.f32 %0, %1;" : "=f"(g) : "f"(arg));
        acc = fmaf(g, q1.w, acc);
    }

    if (m < M) out[m] = acc;
}

extern "C" void kernel_launch(void* const* d_in, const int* in_sizes, int n_in,
                              void* d_out, int out_size) {
    const float* points      = (const float*)d_in[0];  // [M,3]
    const float* positions   = (const float*)d_in[1];  // [N,3]
    const float* log_scales  = (const float*)d_in[2];  // [N,3]
    const float* intensities = (const float*)d_in[3];  // [N]
    float* out = (float*)d_out;

    int M = in_sizes[0] / 3;
    int N = in_sizes[3];

    prep_kernel<<<(N + 255) / 256, 256>>>(positions, log_scales, intensities, N);

    int block = 256;
    int grid = (M + block - 1) / block;
    size_t smem = (size_t)2 * N * sizeof(float4);
    eval_kernel<<<grid, block, smem>>>(points, out, M, N);
}